// round 16
// baseline (speedup 1.0000x reference)
#include <cuda_runtime.h>
#include <cuda_fp16.h>
#include <cstdint>
#include <math.h>

// Problem constants
#define NN   36864
#define NEDG 138240
#define NEC  92160

// ---------------------------------------------------------------------------
// Scratch (fp32 units; fp16 buffers overlay inside)
// ---------------------------------------------------------------------------
__device__ __align__(128) float SCRATCH[153174528];

#define OF_SA   0L           // store (inter_all) fp16, N x 768 halves
#define OF_SB   28311552L    // blocks fp32,            N x 768
#define OF_H    56623104L    // Hb fp16,                N x 256
#define OF_COMB 66060288L    // Cb fp16,                N x 128
#define OF_AGG  70778880L    // agg fp32,               N x 128
#define OF_H0   75497472L    // nf_enc fp16,            N x 128
#define OF_G    80216064L    // [Gf|Gt] fp16,           N x 512
#define OF_WF   99090432L    // weight fp16 frags
#define OF_SBH  100090432L   // Sb fp16 mirror,         N x 768 halves
#define OF_TX   152174592L
#define OF_UV   153174016L   // uv fp16 (512 halves)

// weight fragment offsets (fp16 elements)
#define WF_C1 0
#define WF_C2 65536
#define WF_M1 98304
#define WF_M2 163840
#define WF_U1 196608
#define WF_U2 262144

__device__ __forceinline__ uint32_t pack2h(float a, float b) {
    __half2 h = __floats2half2_rn(a, b);
    return *reinterpret_cast<uint32_t*>(&h);
}

__device__ __forceinline__ void mma_fp16(float* c, const uint32_t* a,
                                         uint32_t b0, uint32_t b1) {
    asm volatile(
        "mma.sync.aligned.m16n8k16.row.col.f32.f16.f16.f32 "
        "{%0,%1,%2,%3}, {%4,%5,%6,%7}, {%8,%9}, {%0,%1,%2,%3};"
        : "+f"(c[0]), "+f"(c[1]), "+f"(c[2]), "+f"(c[3])
        : "r"(a[0]), "r"(a[1]), "r"(a[2]), "r"(a[3]), "r"(b0), "r"(b1));
}

__device__ __forceinline__ void ldsm4(uint32_t* r, uint32_t addr) {
    asm volatile("ldmatrix.sync.aligned.m8n8.x4.shared.b16 {%0,%1,%2,%3}, [%4];"
        : "=r"(r[0]), "=r"(r[1]), "=r"(r[2]), "=r"(r[3]) : "r"(addr));
}

__device__ __forceinline__ uint32_t smem_u32(const void* p) {
    uint32_t a;
    asm("{ .reg .u64 tmp; cvta.to.shared.u64 tmp, %1; cvt.u32.u64 %0, tmp; }"
        : "=r"(a) : "l"(p));
    return a;
}

#define CP16(dst, src) \
    asm volatile("cp.async.ca.shared.global [%0], [%1], 16;" :: "r"(dst), "l"(src) : "memory")
#define CPCOMMIT() asm volatile("cp.async.commit_group;" ::: "memory")

// ---------------------------------------------------------------------------
// Weight fragment precompute: W [K x N] fp32 -> fp16, layout [K/32][Ntot][32]
// ---------------------------------------------------------------------------
__global__ void prep_wfrag(const float* __restrict__ W, int K, int N, int Ntot, int noff,
                           __half* __restrict__ dst)
{
    int idx = blockIdx.x * 256 + threadIdx.x;
    if (idx >= K * N) return;
    int k = idx / N, n = idx - k * N;
    int d = (((k >> 5) * Ntot + (noff + n)) << 5) + (k & 31);
    dst[d] = __float2half_rn(W[idx]);
}

// ---------------------------------------------------------------------------
// Pipelined HMMA GEMM, fp16 single-pass (2-stage double buffer).
// A1 (k<K1): fp16 async (a1half) or fp32 convert. A2 (k>=K1): fp16 async
// (a2half) or fp32 convert. Edge mode: A computed in half2 math from G+uv.
// Output: fp16 / fp32 (+ optional fp16 mirror Cv2) / fp32-atomic (edge_mode).
// zeroBuf: optional buffer zeroed cooperatively at kernel start.
// ---------------------------------------------------------------------------
#define ASTR 40
#define TILEB (128 * ASTR * 2)          // 10240 bytes per tile stage
#define SMEM_DYN (4 * TILEB + 512)      // 41472

__global__ void __launch_bounds__(256, 2) hmma_gemm(
    const void* __restrict__ A1v, long lda1, int a1half,
    const void* __restrict__ A2v, long lda2, int a2half, int K1,
    const __half* __restrict__ Bw, int Nw,
    const float* __restrict__ bias,
    void* __restrict__ Cv, long ldc, int out_half,
    __half* __restrict__ Cv2,
    int K, int relu, int edge_mode,
    const __half* __restrict__ G, const int* __restrict__ fidx,
    const int* __restrict__ tidx, const float* __restrict__ ef,
    const __half* __restrict__ uvh,
    float* __restrict__ zeroBuf, long zeroTotal)
{
    extern __shared__ __align__(16) char dsm[];
    const uint32_t sbase = smem_u32(dsm);
    float* biasS = (float*)(dsm + 4 * TILEB);

    const int tid = threadIdx.x;
    const int m0 = blockIdx.x * 128;
    const int n0 = blockIdx.y * 128;

    if (zeroBuf) {
        int nb = gridDim.x * gridDim.y;
        int bid = blockIdx.y * gridDim.x + blockIdx.x;
        long per = zeroTotal / nb;
        float4* p = (float4*)(zeroBuf + (long)bid * per);
        long n4 = per >> 2;
        for (long i = tid; i < n4; i += 256) p[i] = make_float4(0.f, 0.f, 0.f, 0.f);
    }

    const int ldr = tid & 127;
    const int seg = tid >> 7;
    const int k0 = seg * 16;

    const int warp = tid >> 5;
    const int wm = warp >> 1;
    const int wn = warp & 1;
    const int lane = tid & 31;
    const int qr = lane >> 2;
    const int qc = lane & 3;

    if (tid < 128) biasS[tid] = bias ? bias[n0 + tid] : 0.f;

    int fi = 0, ti = 0; __half2 sc2 = __float2half2_rn(0.f);
    if (edge_mode) {
        int e2 = m0 + ldr;
        int e = (e2 / 90) * 135 + (e2 % 90);
        fi = fidx[e]; ti = tidx[e]; sc2 = __float2half2_rn(ef[e]);
    }

    float acc[2][8][4];
#pragma unroll
    for (int mt = 0; mt < 2; mt++)
#pragma unroll
        for (int nt = 0; nt < 8; nt++)
#pragma unroll
            for (int i = 0; i < 4; i++) acc[mt][nt][i] = 0.f;

    const int laneRow = lane & 15;
    const int laneHalf = (lane >> 4) << 3;
    const uint32_t aoff = ((wm * 32 + laneRow) * ASTR + laneHalf) * 2;
    const uint32_t boff = ((wn * 64 + laneRow) * ASTR + laneHalf) * 2;
    const uint32_t stsOff = (uint32_t)(ldr * ASTR + k0) * 2;
    const int nchunk = K >> 5;

    auto chunkAsync = [&](int kc) -> bool {
        if (edge_mode) return false;
        return (kc * 32 < K1) ? (a1half != 0) : (a2half != 0);
    };
    auto cpA = [&](int kc, int stage) {
        const __half* ga = (kc * 32 < K1)
            ? (const __half*)A1v + (size_t)(m0 + ldr) * lda1 + kc * 32 + k0
            : (const __half*)A2v + (size_t)(m0 + ldr) * lda2 + (kc * 32 - K1) + k0;
        uint32_t da = sbase + stage * TILEB + stsOff;
        CP16(da, ga); CP16(da + 16, ga + 8);
    };
    auto cpB = [&](int kc, int stage) {
        const __half* gh = Bw + (((size_t)kc * Nw) + n0 + ldr) * 32 + k0;
        uint32_t dh = sbase + 2 * TILEB + stage * TILEB + stsOff;
        CP16(dh, gh); CP16(dh + 16, gh + 8);
    };
    auto loadChunk = [&](int kc, uint32_t* h) {
        int kk = kc * 32 + k0;
        if (edge_mode) {
            const __half* gfp = G + (size_t)fi * 512 + kk;
            const __half* gtp = G + (size_t)ti * 512 + 256 + kk;
            const __half* uup = uvh + kk;
            const __half* vvp = uvh + 256 + kk;
            uint4 fa = *(const uint4*)gfp, fb = *(const uint4*)(gfp + 8);
            uint4 ta = *(const uint4*)gtp, tb = *(const uint4*)(gtp + 8);
            uint4 ua = *(const uint4*)uup, ub = *(const uint4*)(uup + 8);
            uint4 va = *(const uint4*)vvp, vb = *(const uint4*)(vvp + 8);
            uint32_t fv[8] = {fa.x, fa.y, fa.z, fa.w, fb.x, fb.y, fb.z, fb.w};
            uint32_t tv[8] = {ta.x, ta.y, ta.z, ta.w, tb.x, tb.y, tb.z, tb.w};
            uint32_t uvv[8] = {ua.x, ua.y, ua.z, ua.w, ub.x, ub.y, ub.z, ub.w};
            uint32_t vv[8] = {va.x, va.y, va.z, va.w, vb.x, vb.y, vb.z, vb.w};
            const __half2 z2 = __float2half2_rn(0.f);
#pragma unroll
            for (int i = 0; i < 8; i++) {
                __half2 f2 = *reinterpret_cast<__half2*>(&fv[i]);
                __half2 t2 = *reinterpret_cast<__half2*>(&tv[i]);
                __half2 u2 = *reinterpret_cast<__half2*>(&uvv[i]);
                __half2 v2 = *reinterpret_cast<__half2*>(&vv[i]);
                __half2 r = __hmax2(__hfma2(sc2, u2, __hadd2(__hadd2(f2, t2), v2)), z2);
                h[i] = *reinterpret_cast<uint32_t*>(&r);
            }
        } else {
            const float* src = (kc * 32 < K1)
                ? (const float*)A1v + (size_t)(m0 + ldr) * lda1 + kk
                : (const float*)A2v + (size_t)(m0 + ldr) * lda2 + (kc * 32 - K1) + k0;
#pragma unroll
            for (int p = 0; p < 4; p++) {
                float4 x = *(const float4*)(src + p * 4);
                h[p * 2]     = pack2h(x.x, x.y);
                h[p * 2 + 1] = pack2h(x.z, x.w);
            }
        }
    };
    auto stsA = [&](int stage, const uint32_t* h) {
        char* dA = dsm + stage * TILEB + stsOff;
        ((uint4*)dA)[0] = make_uint4(h[0], h[1], h[2], h[3]);
        ((uint4*)dA)[1] = make_uint4(h[4], h[5], h[6], h[7]);
    };

    // prologue: chunk 0
    {
        bool as0 = chunkAsync(0);
        if (as0) cpA(0, 0);
        cpB(0, 0);
        CPCOMMIT();
        if (!as0) {
            uint32_t h[8];
            loadChunk(0, h);
            stsA(0, h);
        }
    }

    for (int kc = 0; kc < nchunk; kc++) {
        const int cur = kc & 1, nxt = cur ^ 1;
        const bool haveNext = (kc + 1 < nchunk);
        const bool nxtAsync = haveNext && chunkAsync(kc + 1);
        const bool nxtConv = haveNext && !chunkAsync(kc + 1);
        uint32_t hn[8];
        if (nxtConv) loadChunk(kc + 1, hn);

        asm volatile("cp.async.wait_group 0;" ::: "memory");
        __syncthreads();
        if (haveNext) {
            if (nxtAsync) cpA(kc + 1, nxt);
            cpB(kc + 1, nxt);
            CPCOMMIT();
        }

        const uint32_t aT = sbase + cur * TILEB;
        const uint32_t bT = sbase + 2 * TILEB + cur * TILEB;
#pragma unroll
        for (int ks = 0; ks < 2; ks++) {
            uint32_t Ah[2][4];
            ldsm4(Ah[0], aT + aoff + ks * 32);
            ldsm4(Ah[1], aT + aoff + 16 * ASTR * 2 + ks * 32);
#pragma unroll
            for (int np = 0; np < 4; np++) {
                uint32_t Bv[4];
                ldsm4(Bv, bT + boff + np * 16 * ASTR * 2 + ks * 32);
#pragma unroll
                for (int mt = 0; mt < 2; mt++) {
                    mma_fp16(acc[mt][2 * np],     Ah[mt], Bv[0], Bv[2]);
                    mma_fp16(acc[mt][2 * np + 1], Ah[mt], Bv[1], Bv[3]);
                }
            }
        }
        if (nxtConv) stsA(nxt, hn);
    }

    // epilogue
    if (edge_mode) {
        float* C = (float*)Cv;
#pragma unroll
        for (int mt = 0; mt < 2; mt++) {
            int r1 = m0 + wm * 32 + mt * 16 + qr;
            int r2 = r1 + 8;
            int e1 = (r1 / 90) * 135 + (r1 % 90);
            int e2 = (r2 / 90) * 135 + (r2 % 90);
            size_t t1 = (size_t)tidx[e1] * ldc;
            size_t t2 = (size_t)tidx[e2] * ldc;
#pragma unroll
            for (int nt = 0; nt < 8; nt++) {
                int coll = wn * 64 + nt * 8 + qc * 2;
                float b0 = biasS[coll], b1 = biasS[coll + 1];
                atomicAdd(&C[t1 + coll],     acc[mt][nt][0] + b0);
                atomicAdd(&C[t1 + coll + 1], acc[mt][nt][1] + b1);
                atomicAdd(&C[t2 + coll],     acc[mt][nt][2] + b0);
                atomicAdd(&C[t2 + coll + 1], acc[mt][nt][3] + b1);
            }
        }
    } else if (out_half) {
        __half* C = (__half*)Cv;
#pragma unroll
        for (int mt = 0; mt < 2; mt++) {
            int row = m0 + wm * 32 + mt * 16 + qr;
#pragma unroll
            for (int nt = 0; nt < 8; nt++) {
                int coll = wn * 64 + nt * 8 + qc * 2;
                float b0 = biasS[coll], b1 = biasS[coll + 1];
                float v00 = acc[mt][nt][0] + b0, v01 = acc[mt][nt][1] + b1;
                float v10 = acc[mt][nt][2] + b0, v11 = acc[mt][nt][3] + b1;
                if (relu) {
                    v00 = fmaxf(v00, 0.f); v01 = fmaxf(v01, 0.f);
                    v10 = fmaxf(v10, 0.f); v11 = fmaxf(v11, 0.f);
                }
                *(__half2*)(C + (size_t)row * ldc + n0 + coll) = __floats2half2_rn(v00, v01);
                *(__half2*)(C + (size_t)(row + 8) * ldc + n0 + coll) = __floats2half2_rn(v10, v11);
            }
        }
    } else {
        float* C = (float*)Cv;
#pragma unroll
        for (int mt = 0; mt < 2; mt++) {
            int row = m0 + wm * 32 + mt * 16 + qr;
#pragma unroll
            for (int nt = 0; nt < 8; nt++) {
                int coll = wn * 64 + nt * 8 + qc * 2;
                float b0 = biasS[coll], b1 = biasS[coll + 1];
                float2 v0, v1;
                v0.x = acc[mt][nt][0] + b0; v0.y = acc[mt][nt][1] + b1;
                v1.x = acc[mt][nt][2] + b0; v1.y = acc[mt][nt][3] + b1;
                if (relu) {
                    v0.x = fmaxf(v0.x, 0.f); v0.y = fmaxf(v0.y, 0.f);
                    v1.x = fmaxf(v1.x, 0.f); v1.y = fmaxf(v1.y, 0.f);
                }
                *(float2*)(C + (size_t)row * ldc + n0 + coll) = v0;
                *(float2*)(C + (size_t)(row + 8) * ldc + n0 + coll) = v1;
                if (Cv2) {
                    *(__half2*)(Cv2 + (size_t)row * ldc + n0 + coll) = __floats2half2_rn(v0.x, v0.y);
                    *(__half2*)(Cv2 + (size_t)(row + 8) * ldc + n0 + coll) = __floats2half2_rn(v1.x, v1.y);
                }
            }
        }
    }
}

// ---------------------------------------------------------------------------
// Small kernels
// ---------------------------------------------------------------------------
__global__ void prep_uv(const float* __restrict__ W_ee, const float* __restrict__ b_ee,
                        const float* __restrict__ W_m1, const float* __restrict__ b_m1,
                        __half* __restrict__ uvh)
{
    int j = threadIdx.x;
    float u = 0.f, v = 0.f;
    for (int d = 0; d < 128; ++d) {
        float w = W_m1[(size_t)(256 + d) * 256 + j];
        u += W_ee[d] * w;
        v += b_ee[d] * w;
    }
    uvh[j] = __float2half_rn(u);
    uvh[256 + j] = __float2half_rn(v + b_m1[j]);
}

__global__ void node_enc(const float* __restrict__ nf, const float* __restrict__ W_ne,
                         const float* __restrict__ b_ne, __half* __restrict__ h0)
{
    int idx = blockIdx.x * 256 + threadIdx.x;
    int i = idx >> 7, d = idx & 127;
    h0[idx] = __float2half_rn(nf[i] * W_ne[d] + b_ne[d]);
}

__global__ void zero_sb0(float* __restrict__ Sb)
{
    int idx = blockIdx.x * 256 + threadIdx.x;
    Sb[(size_t)(idx >> 7) * 768 + (idx & 127)] = 0.f;
}

__global__ void transform_k(const float* __restrict__ Sb,
                            const float* __restrict__ W1, const float* __restrict__ B1,
                            const float* __restrict__ W2, const float* __restrict__ B2,
                            float* __restrict__ tx)
{
    __shared__ float hs[8][16];
    int r = threadIdx.x >> 4;
    int j = threadIdx.x & 15;
    size_t row = (size_t)blockIdx.x * 8 + r;
    const float* x = Sb + row * 768 + 640;
    float acc = B1[j];
#pragma unroll 4
    for (int k = 0; k < 128; k++) acc += x[k] * W1[k * 16 + j];
    hs[r][j] = fmaxf(acc, 0.f);
    __syncthreads();
    float o = B2[j];
#pragma unroll
    for (int i = 0; i < 16; i++) o += hs[r][i] * W2[i * 16 + j];
    tx[row * 16 + j] = o;
}

// ---------------------------------------------------------------------------
// match_k: Sinkhorn (in smem) + either apply-plan (mode 0, writes Sa fp16)
// or score (mode 1, writes out). One block per pair, 256 threads.
// ---------------------------------------------------------------------------
__global__ void match_k(const float* __restrict__ tx, const float* __restrict__ Sb,
                        __half* __restrict__ Sa, float* __restrict__ out, int mode)
{
    __shared__ float mq[20][16], mc[20][16], la[20][20], red[256];
    __shared__ float tile[18][256];
    int b = blockIdx.x, t = threadIdx.x;  // 256 threads
    for (int i = t; i < 320; i += 256) {
        int r = i >> 4, c = i & 15;
        mq[r][c] = (r < 15) ? tx[((size_t)(2 * b) * 18 + r) * 16 + c] : 0.f;
        mc[r][c] = (r < 18) ? tx[((size_t)(2 * b + 1) * 18 + r) * 16 + c] : 0.f;
    }
    __syncthreads();
    for (int i = t; i < 400; i += 256) {
        int q = i / 20, c = i % 20;
        float s = 0.f;
#pragma unroll
        for (int k = 0; k < 16; k++) s += mq[q][k] * mc[c][k];
        la[q][c] = s * 10.f;  // / SINKHORN_TEMP
    }
    __syncthreads();
    for (int it = 0; it < 10; ++it) {
        if (t < 20) {
            float m = -1e30f;
            for (int c = 0; c < 20; c++) m = fmaxf(m, la[t][c]);
            float s = 0.f;
            for (int c = 0; c < 20; c++) s += expf(la[t][c] - m);
            red[t] = logf(s) + m;
        }
        __syncthreads();
        for (int i = t; i < 400; i += 256) la[i / 20][i % 20] -= red[i / 20];
        __syncthreads();
        if (t < 20) {
            float m = -1e30f;
            for (int q = 0; q < 20; q++) m = fmaxf(m, la[q][t]);
            float s = 0.f;
            for (int q = 0; q < 20; q++) s += expf(la[q][t] - m);
            red[t] = logf(s) + m;
        }
        __syncthreads();
        for (int i = t; i < 400; i += 256) la[i / 20][i % 20] -= red[i % 20];
        __syncthreads();
    }
    for (int i = t; i < 400; i += 256) la[i / 20][i % 20] = expf(la[i / 20][i % 20]);
    __syncthreads();

    if (mode == 0) {
        // apply plan to both sides, fp16 output
        for (int side = 0; side < 2; side++) {
            size_t in_base  = ((size_t)(2 * b) + (side == 0 ? 1 : 0)) * 18 * 768;
            size_t out_base = ((size_t)(2 * b) + side) * 18 * 768;
            for (int ch = 0; ch < 3; ch++) {
                __syncthreads();
                int c0 = ch * 256;
                for (int i = t; i < 1152; i += 256) {
                    int r = i / 64, q = i % 64;
                    reinterpret_cast<float4*>(&tile[r][0])[q] =
                        *reinterpret_cast<const float4*>(&Sb[in_base + (size_t)r * 768 + c0 + q * 4]);
                }
                __syncthreads();
                for (int s = 0; s < 18; s++) {
                    float acc = 0.f;
#pragma unroll
                    for (int r = 0; r < 18; r++) {
                        float wv = (side == 0) ? la[s][r] : la[r][s];
                        acc += wv * tile[r][t];
                    }
                    Sa[out_base + (size_t)s * 768 + c0 + t] = __float2half_rn(acc);
                }
            }
        }
    } else {
        // score: -sum_{q<20,k<16} relu(mq - plan @ mc)  (padded q rows DO contribute)
        float local = 0.f;
        for (int i = t; i < 320; i += 256) {
            int q = i >> 4, k = i & 15;
            float pm = 0.f;
#pragma unroll
            for (int c = 0; c < 20; c++) pm += la[q][c] * mc[c][k];
            local += fmaxf(mq[q][k] - pm, 0.f);
        }
        red[t] = local;
        __syncthreads();
        for (int s = 128; s > 0; s >>= 1) {
            if (t < s) red[t] += red[t + s];
            __syncthreads();
        }
        if (t == 0) out[b] = -red[0];
    }
}

// ---------------------------------------------------------------------------
// Launch
// ---------------------------------------------------------------------------
extern "C" void kernel_launch(void* const* d_in, const int* in_sizes, int n_in,
                              void* d_out, int out_size)
{
    const float* node_features = (const float*)d_in[0];
    const float* edge_features = (const float*)d_in[1];
    const float* mult          = (const float*)d_in[2];  (void)mult;
    const float* W_ne = (const float*)d_in[3];  const float* b_ne = (const float*)d_in[4];
    const float* W_ee = (const float*)d_in[5];  const float* b_ee = (const float*)d_in[6];
    const float* W_m1 = (const float*)d_in[7];  const float* b_m1 = (const float*)d_in[8];
    const float* W_m2 = (const float*)d_in[9];  const float* b_m2 = (const float*)d_in[10];
    const float* W_u1 = (const float*)d_in[11]; const float* b_u1 = (const float*)d_in[12];
    const float* W_u2 = (const float*)d_in[13]; const float* b_u2 = (const float*)d_in[14];
    const float* W_c1 = (const float*)d_in[15]; const float* b_c1 = (const float*)d_in[16];
    const float* W_c2 = (const float*)d_in[17]; const float* b_c2 = (const float*)d_in[18];
    const float* W_t1 = (const float*)d_in[19]; const float* b_t1 = (const float*)d_in[20];
    const float* W_t2 = (const float*)d_in[21]; const float* b_t2 = (const float*)d_in[22];
    const int* from_idx = (const int*)d_in[23];
    const int* to_idx   = (const int*)d_in[24];
    float* out = (float*)d_out;

    cudaFuncSetAttribute(hmma_gemm, cudaFuncAttributeMaxDynamicSharedMemorySize, SMEM_DYN);

    float* scratch = nullptr;
    cudaGetSymbolAddress((void**)&scratch, SCRATCH);
    __half* SaH = (__half*)(scratch + OF_SA);
    float* Sb = scratch + OF_SB;
    __half* SbH = (__half*)(scratch + OF_SBH);
    __half* Hb = (__half*)(scratch + OF_H);
    __half* Cb = (__half*)(scratch + OF_COMB);
    float* Ag = scratch + OF_AGG;
    __half* H0 = (__half*)(scratch + OF_H0);
    __half* Gb = (__half*)(scratch + OF_G);
    float* Tx = scratch + OF_TX;
    __half* Uv = (__half*)(scratch + OF_UV);
    __half* WF = (__half*)(scratch + OF_WF);

    // --- init (launch index 3 = first hmma_gemm) ---
    node_enc<<<18432, 256>>>(node_features, W_ne, b_ne, H0);
    prep_uv<<<1, 256>>>(W_ee, b_ee, W_m1, b_m1, Uv);
    prep_wfrag<<<256, 256>>>(W_c1, 256, 256, 256, 0, WF + WF_C1);
    // t=0, p=1: A1 = H0 (fp16), K=128 (inter == 0)
    hmma_gemm<<<dim3(288, 2), 256, SMEM_DYN>>>(
        H0, 128, 1, nullptr, 0, 0, 128,
        WF + WF_C1, 256, b_c1, Hb, 256, 1, nullptr, 128, 1, 0,
        nullptr, nullptr, nullptr, nullptr, nullptr, nullptr, 0);
    prep_wfrag<<<128, 256>>>(W_c2, 256, 128, 128, 0, WF + WF_C2);
    prep_wfrag<<<128, 256>>>(W_m1, 128, 256, 512, 0, WF + WF_M1);
    prep_wfrag<<<128, 256>>>(W_m1 + 128 * 256, 128, 256, 512, 256, WF + WF_M1);
    prep_wfrag<<<128, 256>>>(W_m2, 256, 128, 128, 0, WF + WF_M2);
    prep_wfrag<<<256, 256>>>(W_u1, 256, 256, 256, 0, WF + WF_U1);
    prep_wfrag<<<128, 256>>>(W_u2, 256, 128, 128, 0, WF + WF_U2);
    zero_sb0<<<18432, 256>>>(Sb);

    for (int t = 0; t < 3; t++) {
        for (int p = 1; p <= 5; p++) {
            // C1: Hb = relu([h, inter] @ W_c1 + b_c1) — all-async A
            if (!(t == 0 && p == 1)) {
                const void* hsrc = (p == 1) ? (const void*)H0
                                            : (const void*)(SbH + (size_t)(p - 1) * 128);
                int kC1 = (t == 0) ? 128 : 256;
                hmma_gemm<<<dim3(288, 2), 256, SMEM_DYN>>>(
                    hsrc, (p == 1) ? 128L : 768L, 1, SaH + (size_t)(p - 1) * 128, 768, 1, 128,
                    WF + WF_C1, 256, b_c1, Hb, 256, 1, nullptr, kC1, 1, 0,
                    nullptr, nullptr, nullptr, nullptr, nullptr, nullptr, 0);
            }
            // C2: Cb = Hb @ W_c2 + b_c2 (fp16 in/out)
            hmma_gemm<<<dim3(288, 1), 256, SMEM_DYN>>>(
                Hb, 256, 1, nullptr, 0, 0, 256,
                WF + WF_C2, 128, b_c2, Cb, 128, 1, nullptr, 256, 0, 0,
                nullptr, nullptr, nullptr, nullptr, nullptr, nullptr, 0);
            // M1: Gb = Cb @ [W_m1a | W_m1b] (fp16 in/out, N=512); also zero Ag
            hmma_gemm<<<dim3(288, 4), 256, SMEM_DYN>>>(
                Cb, 128, 1, nullptr, 0, 0, 128,
                WF + WF_M1, 512, nullptr, Gb, 512, 1, nullptr, 128, 0, 0,
                nullptr, nullptr, nullptr, nullptr, nullptr, Ag, 4718592L);
            // edge GEMM -> fp32 atomic agg (fp16 gathers)
            hmma_gemm<<<dim3(720, 1), 256, SMEM_DYN>>>(
                nullptr, 0, 0, nullptr, 0, 0, 256,
                WF + WF_M2, 128, b_m2, Ag, 128, 0, nullptr, 256, 0, 1,
                Gb, from_idx, to_idx, edge_features, Uv, nullptr, 0);
            // U1: Hb = relu([Cb(fp16), Ag(fp32)] @ W_u1 + b_u1)
            hmma_gemm<<<dim3(288, 2), 256, SMEM_DYN>>>(
                Cb, 128, 1, Ag, 128, 0, 128,
                WF + WF_U1, 256, b_u1, Hb, 256, 1, nullptr, 256, 1, 0,
                nullptr, nullptr, nullptr, nullptr, nullptr, nullptr, 0);
            // U2: Sb block p (fp32) + SbH mirror (fp16) = Hb @ W_u2 + b_u2
            hmma_gemm<<<dim3(288, 1), 256, SMEM_DYN>>>(
                Hb, 256, 1, nullptr, 0, 0, 256,
                WF + WF_U2, 128, b_u2, Sb + (size_t)p * 128, 768, 0,
                SbH + (size_t)p * 128, 256, 0, 0,
                nullptr, nullptr, nullptr, nullptr, nullptr, nullptr, 0);
        }
        transform_k<<<4608, 128>>>(Sb, W_t1, b_t1, W_t2, b_t2, Tx);
        // sinkhorn (+apply at t<2, +score at t=2) fused
        match_k<<<1024, 256>>>(Tx, Sb, SaH, out, (t < 2) ? 0 : 1);
    }
}

// round 17
// speedup vs baseline: 1.0196x; 1.0196x over previous
#include <cuda_runtime.h>
#include <cuda_fp16.h>
#include <cstdint>
#include <math.h>

// Problem constants
#define NN   36864
#define NEDG 138240
#define NEC  92160

// ---------------------------------------------------------------------------
// Scratch (fp32 units; fp16 buffers overlay inside)
// ---------------------------------------------------------------------------
__device__ __align__(128) float SCRATCH[153174528];

#define OF_SA   0L           // store (inter_all) fp16, N x 768 halves
#define OF_SB   28311552L    // blocks fp32,            N x 768
#define OF_H    56623104L    // Hb fp16,                N x 256
#define OF_COMB 66060288L    // Cb fp16,                N x 128
#define OF_AGG  70778880L    // agg fp32,               N x 128
#define OF_H0   75497472L    // nf_enc fp16,            N x 128
#define OF_G    80216064L    // [Gf|Gt] fp16,           N x 512
#define OF_WF   99090432L    // weight fp16 frags
#define OF_SBH  100090432L   // Sb fp16 mirror,         N x 768 halves
#define OF_TX   152174592L
#define OF_UV   153174016L   // uv fp16 (512 halves)

// weight fragment offsets (fp16 elements)
#define WF_C1 0
#define WF_C2 65536
#define WF_M1 98304
#define WF_M2 163840
#define WF_U1 196608
#define WF_U2 262144

__device__ __forceinline__ uint32_t pack2h(float a, float b) {
    __half2 h = __floats2half2_rn(a, b);
    return *reinterpret_cast<uint32_t*>(&h);
}

__device__ __forceinline__ void mma_fp16(float* c, const uint32_t* a,
                                         uint32_t b0, uint32_t b1) {
    asm volatile(
        "mma.sync.aligned.m16n8k16.row.col.f32.f16.f16.f32 "
        "{%0,%1,%2,%3}, {%4,%5,%6,%7}, {%8,%9}, {%0,%1,%2,%3};"
        : "+f"(c[0]), "+f"(c[1]), "+f"(c[2]), "+f"(c[3])
        : "r"(a[0]), "r"(a[1]), "r"(a[2]), "r"(a[3]), "r"(b0), "r"(b1));
}

__device__ __forceinline__ void ldsm4(uint32_t* r, uint32_t addr) {
    asm volatile("ldmatrix.sync.aligned.m8n8.x4.shared.b16 {%0,%1,%2,%3}, [%4];"
        : "=r"(r[0]), "=r"(r[1]), "=r"(r[2]), "=r"(r[3]) : "r"(addr));
}

__device__ __forceinline__ uint32_t smem_u32(const void* p) {
    uint32_t a;
    asm("{ .reg .u64 tmp; cvta.to.shared.u64 tmp, %1; cvt.u32.u64 %0, tmp; }"
        : "=r"(a) : "l"(p));
    return a;
}

#define CP16(dst, src) \
    asm volatile("cp.async.ca.shared.global [%0], [%1], 16;" :: "r"(dst), "l"(src) : "memory")
#define CPCOMMIT() asm volatile("cp.async.commit_group;" ::: "memory")

// ---------------------------------------------------------------------------
// Weight fragment precompute: W [K x N] fp32 -> fp16, layout [K/32][Ntot][32]
// ---------------------------------------------------------------------------
__global__ void prep_wfrag(const float* __restrict__ W, int K, int N, int Ntot, int noff,
                           __half* __restrict__ dst)
{
    int idx = blockIdx.x * 256 + threadIdx.x;
    if (idx >= K * N) return;
    int k = idx / N, n = idx - k * N;
    int d = (((k >> 5) * Ntot + (noff + n)) << 5) + (k & 31);
    dst[d] = __float2half_rn(W[idx]);
}

// ---------------------------------------------------------------------------
// Pipelined HMMA GEMM, fp16 single-pass, 3-stage cp.async pipeline (depth 2).
// A1 (k<K1): fp16 async (a1half) or fp32 convert. A2 (k>=K1): fp16 async
// (a2half) or fp32 convert. Edge mode: A computed in half2 math from G+uv.
// Output: fp16 / fp32 (+ optional fp16 mirror Cv2) / fp32-atomic (edge_mode).
// zeroBuf: optional buffer zeroed cooperatively at kernel start.
// ---------------------------------------------------------------------------
#define ASTR 40
#define TILEB (128 * ASTR * 2)          // 10240 bytes per tile stage
#define NSTG 3
#define SMEM_DYN (2 * NSTG * TILEB + 512)   // 61952

__global__ void __launch_bounds__(256, 2) hmma_gemm(
    const void* __restrict__ A1v, long lda1, int a1half,
    const void* __restrict__ A2v, long lda2, int a2half, int K1,
    const __half* __restrict__ Bw, int Nw,
    const float* __restrict__ bias,
    void* __restrict__ Cv, long ldc, int out_half,
    __half* __restrict__ Cv2,
    int K, int relu, int edge_mode,
    const __half* __restrict__ G, const int* __restrict__ fidx,
    const int* __restrict__ tidx, const float* __restrict__ ef,
    const __half* __restrict__ uvh,
    float* __restrict__ zeroBuf, long zeroTotal)
{
    extern __shared__ __align__(16) char dsm[];
    const uint32_t sbase = smem_u32(dsm);
    float* biasS = (float*)(dsm + 2 * NSTG * TILEB);

    const int tid = threadIdx.x;
    const int m0 = blockIdx.x * 128;
    const int n0 = blockIdx.y * 128;

    if (zeroBuf) {
        int nb = gridDim.x * gridDim.y;
        int bid = blockIdx.y * gridDim.x + blockIdx.x;
        long per = zeroTotal / nb;
        float4* p = (float4*)(zeroBuf + (long)bid * per);
        long n4 = per >> 2;
        for (long i = tid; i < n4; i += 256) p[i] = make_float4(0.f, 0.f, 0.f, 0.f);
    }

    const int ldr = tid & 127;
    const int seg = tid >> 7;
    const int k0 = seg * 16;

    const int warp = tid >> 5;
    const int wm = warp >> 1;
    const int wn = warp & 1;
    const int lane = tid & 31;
    const int qr = lane >> 2;
    const int qc = lane & 3;

    if (tid < 128) biasS[tid] = bias ? bias[n0 + tid] : 0.f;

    int fi = 0, ti = 0; __half2 sc2 = __float2half2_rn(0.f);
    if (edge_mode) {
        int e2 = m0 + ldr;
        int e = (e2 / 90) * 135 + (e2 % 90);
        fi = fidx[e]; ti = tidx[e]; sc2 = __float2half2_rn(ef[e]);
    }

    float acc[2][8][4];
#pragma unroll
    for (int mt = 0; mt < 2; mt++)
#pragma unroll
        for (int nt = 0; nt < 8; nt++)
#pragma unroll
            for (int i = 0; i < 4; i++) acc[mt][nt][i] = 0.f;

    const int laneRow = lane & 15;
    const int laneHalf = (lane >> 4) << 3;
    const uint32_t aoff = ((wm * 32 + laneRow) * ASTR + laneHalf) * 2;
    const uint32_t boff = ((wn * 64 + laneRow) * ASTR + laneHalf) * 2;
    const uint32_t stsOff = (uint32_t)(ldr * ASTR + k0) * 2;
    const int nchunk = K >> 5;

    auto chunkAsync = [&](int kc) -> bool {
        if (edge_mode) return false;
        return (kc * 32 < K1) ? (a1half != 0) : (a2half != 0);
    };
    auto cpA = [&](int kc, int stage) {
        const __half* ga = (kc * 32 < K1)
            ? (const __half*)A1v + (size_t)(m0 + ldr) * lda1 + kc * 32 + k0
            : (const __half*)A2v + (size_t)(m0 + ldr) * lda2 + (kc * 32 - K1) + k0;
        uint32_t da = sbase + stage * TILEB + stsOff;
        CP16(da, ga); CP16(da + 16, ga + 8);
    };
    auto cpB = [&](int kc, int stage) {
        const __half* gh = Bw + (((size_t)kc * Nw) + n0 + ldr) * 32 + k0;
        uint32_t dh = sbase + NSTG * TILEB + stage * TILEB + stsOff;
        CP16(dh, gh); CP16(dh + 16, gh + 8);
    };
    auto issueChunk = [&](int kc) {
        int stage = kc % NSTG;
        if (chunkAsync(kc)) cpA(kc, stage);
        cpB(kc, stage);
        CPCOMMIT();
    };
    auto loadChunk = [&](int kc, uint32_t* h) {
        int kk = kc * 32 + k0;
        if (edge_mode) {
            const __half* gfp = G + (size_t)fi * 512 + kk;
            const __half* gtp = G + (size_t)ti * 512 + 256 + kk;
            const __half* uup = uvh + kk;
            const __half* vvp = uvh + 256 + kk;
            uint4 fa = *(const uint4*)gfp, fb = *(const uint4*)(gfp + 8);
            uint4 ta = *(const uint4*)gtp, tb = *(const uint4*)(gtp + 8);
            uint4 ua = *(const uint4*)uup, ub = *(const uint4*)(uup + 8);
            uint4 va = *(const uint4*)vvp, vb = *(const uint4*)(vvp + 8);
            uint32_t fv[8] = {fa.x, fa.y, fa.z, fa.w, fb.x, fb.y, fb.z, fb.w};
            uint32_t tv[8] = {ta.x, ta.y, ta.z, ta.w, tb.x, tb.y, tb.z, tb.w};
            uint32_t uvv[8] = {ua.x, ua.y, ua.z, ua.w, ub.x, ub.y, ub.z, ub.w};
            uint32_t vv[8] = {va.x, va.y, va.z, va.w, vb.x, vb.y, vb.z, vb.w};
            const __half2 z2 = __float2half2_rn(0.f);
#pragma unroll
            for (int i = 0; i < 8; i++) {
                __half2 f2 = *reinterpret_cast<__half2*>(&fv[i]);
                __half2 t2 = *reinterpret_cast<__half2*>(&tv[i]);
                __half2 u2 = *reinterpret_cast<__half2*>(&uvv[i]);
                __half2 v2 = *reinterpret_cast<__half2*>(&vv[i]);
                __half2 r = __hmax2(__hfma2(sc2, u2, __hadd2(__hadd2(f2, t2), v2)), z2);
                h[i] = *reinterpret_cast<uint32_t*>(&r);
            }
        } else {
            const float* src = (kc * 32 < K1)
                ? (const float*)A1v + (size_t)(m0 + ldr) * lda1 + kk
                : (const float*)A2v + (size_t)(m0 + ldr) * lda2 + (kc * 32 - K1) + k0;
#pragma unroll
            for (int p = 0; p < 4; p++) {
                float4 x = *(const float4*)(src + p * 4);
                h[p * 2]     = pack2h(x.x, x.y);
                h[p * 2 + 1] = pack2h(x.z, x.w);
            }
        }
    };
    auto stsA = [&](int stage, const uint32_t* h) {
        char* dA = dsm + (size_t)stage * TILEB + stsOff;
        ((uint4*)dA)[0] = make_uint4(h[0], h[1], h[2], h[3]);
        ((uint4*)dA)[1] = make_uint4(h[4], h[5], h[6], h[7]);
    };

    // prologue: issue chunks 0 and 1; conv-fill chunk 0
    {
        issueChunk(0);
        if (nchunk > 1) issueChunk(1);
        if (!chunkAsync(0)) {
            uint32_t h[8];
            loadChunk(0, h);
            stsA(0, h);
        }
    }

    for (int kc = 0; kc < nchunk; kc++) {
        const int cur = kc % NSTG;
        const bool haveN1 = (kc + 1 < nchunk);
        const bool haveN2 = (kc + 2 < nchunk);
        const bool convN1 = haveN1 && !chunkAsync(kc + 1);
        uint32_t hn[8];
        if (convN1) loadChunk(kc + 1, hn);

        // ensure chunk kc's copy landed: allow 1 in-flight group if one exists
        if (haveN1) asm volatile("cp.async.wait_group 1;" ::: "memory");
        else       asm volatile("cp.async.wait_group 0;" ::: "memory");
        __syncthreads();
        if (haveN2) issueChunk(kc + 2);
        if (convN1) stsA((kc + 1) % NSTG, hn);

        const uint32_t aT = sbase + cur * TILEB;
        const uint32_t bT = sbase + NSTG * TILEB + cur * TILEB;
#pragma unroll
        for (int ks = 0; ks < 2; ks++) {
            uint32_t Ah[2][4];
            ldsm4(Ah[0], aT + aoff + ks * 32);
            ldsm4(Ah[1], aT + aoff + 16 * ASTR * 2 + ks * 32);
#pragma unroll
            for (int np = 0; np < 4; np++) {
                uint32_t Bv[4];
                ldsm4(Bv, bT + boff + np * 16 * ASTR * 2 + ks * 32);
#pragma unroll
                for (int mt = 0; mt < 2; mt++) {
                    mma_fp16(acc[mt][2 * np],     Ah[mt], Bv[0], Bv[2]);
                    mma_fp16(acc[mt][2 * np + 1], Ah[mt], Bv[1], Bv[3]);
                }
            }
        }
    }

    // epilogue
    if (edge_mode) {
        float* C = (float*)Cv;
#pragma unroll
        for (int mt = 0; mt < 2; mt++) {
            int r1 = m0 + wm * 32 + mt * 16 + qr;
            int r2 = r1 + 8;
            int e1 = (r1 / 90) * 135 + (r1 % 90);
            int e2 = (r2 / 90) * 135 + (r2 % 90);
            size_t t1 = (size_t)tidx[e1] * ldc;
            size_t t2 = (size_t)tidx[e2] * ldc;
#pragma unroll
            for (int nt = 0; nt < 8; nt++) {
                int coll = wn * 64 + nt * 8 + qc * 2;
                float b0 = biasS[coll], b1 = biasS[coll + 1];
                atomicAdd(&C[t1 + coll],     acc[mt][nt][0] + b0);
                atomicAdd(&C[t1 + coll + 1], acc[mt][nt][1] + b1);
                atomicAdd(&C[t2 + coll],     acc[mt][nt][2] + b0);
                atomicAdd(&C[t2 + coll + 1], acc[mt][nt][3] + b1);
            }
        }
    } else if (out_half) {
        __half* C = (__half*)Cv;
#pragma unroll
        for (int mt = 0; mt < 2; mt++) {
            int row = m0 + wm * 32 + mt * 16 + qr;
#pragma unroll
            for (int nt = 0; nt < 8; nt++) {
                int coll = wn * 64 + nt * 8 + qc * 2;
                float b0 = biasS[coll], b1 = biasS[coll + 1];
                float v00 = acc[mt][nt][0] + b0, v01 = acc[mt][nt][1] + b1;
                float v10 = acc[mt][nt][2] + b0, v11 = acc[mt][nt][3] + b1;
                if (relu) {
                    v00 = fmaxf(v00, 0.f); v01 = fmaxf(v01, 0.f);
                    v10 = fmaxf(v10, 0.f); v11 = fmaxf(v11, 0.f);
                }
                *(__half2*)(C + (size_t)row * ldc + n0 + coll) = __floats2half2_rn(v00, v01);
                *(__half2*)(C + (size_t)(row + 8) * ldc + n0 + coll) = __floats2half2_rn(v10, v11);
            }
        }
    } else {
        float* C = (float*)Cv;
#pragma unroll
        for (int mt = 0; mt < 2; mt++) {
            int row = m0 + wm * 32 + mt * 16 + qr;
#pragma unroll
            for (int nt = 0; nt < 8; nt++) {
                int coll = wn * 64 + nt * 8 + qc * 2;
                float b0 = biasS[coll], b1 = biasS[coll + 1];
                float2 v0, v1;
                v0.x = acc[mt][nt][0] + b0; v0.y = acc[mt][nt][1] + b1;
                v1.x = acc[mt][nt][2] + b0; v1.y = acc[mt][nt][3] + b1;
                if (relu) {
                    v0.x = fmaxf(v0.x, 0.f); v0.y = fmaxf(v0.y, 0.f);
                    v1.x = fmaxf(v1.x, 0.f); v1.y = fmaxf(v1.y, 0.f);
                }
                *(float2*)(C + (size_t)row * ldc + n0 + coll) = v0;
                *(float2*)(C + (size_t)(row + 8) * ldc + n0 + coll) = v1;
                if (Cv2) {
                    *(__half2*)(Cv2 + (size_t)row * ldc + n0 + coll) = __floats2half2_rn(v0.x, v0.y);
                    *(__half2*)(Cv2 + (size_t)(row + 8) * ldc + n0 + coll) = __floats2half2_rn(v1.x, v1.y);
                }
            }
        }
    }
}

// ---------------------------------------------------------------------------
// Small kernels
// ---------------------------------------------------------------------------
__global__ void prep_uv(const float* __restrict__ W_ee, const float* __restrict__ b_ee,
                        const float* __restrict__ W_m1, const float* __restrict__ b_m1,
                        __half* __restrict__ uvh)
{
    int j = threadIdx.x;
    float u = 0.f, v = 0.f;
    for (int d = 0; d < 128; ++d) {
        float w = W_m1[(size_t)(256 + d) * 256 + j];
        u += W_ee[d] * w;
        v += b_ee[d] * w;
    }
    uvh[j] = __float2half_rn(u);
    uvh[256 + j] = __float2half_rn(v + b_m1[j]);
}

__global__ void node_enc(const float* __restrict__ nf, const float* __restrict__ W_ne,
                         const float* __restrict__ b_ne, __half* __restrict__ h0)
{
    int idx = blockIdx.x * 256 + threadIdx.x;
    int i = idx >> 7, d = idx & 127;
    h0[idx] = __float2half_rn(nf[i] * W_ne[d] + b_ne[d]);
}

__global__ void zero_sb0(float* __restrict__ Sb)
{
    int idx = blockIdx.x * 256 + threadIdx.x;
    Sb[(size_t)(idx >> 7) * 768 + (idx & 127)] = 0.f;
}

__global__ void transform_k(const float* __restrict__ Sb,
                            const float* __restrict__ W1, const float* __restrict__ B1,
                            const float* __restrict__ W2, const float* __restrict__ B2,
                            float* __restrict__ tx)
{
    __shared__ float hs[8][16];
    int r = threadIdx.x >> 4;
    int j = threadIdx.x & 15;
    size_t row = (size_t)blockIdx.x * 8 + r;
    const float* x = Sb + row * 768 + 640;
    float acc = B1[j];
#pragma unroll 4
    for (int k = 0; k < 128; k++) acc += x[k] * W1[k * 16 + j];
    hs[r][j] = fmaxf(acc, 0.f);
    __syncthreads();
    float o = B2[j];
#pragma unroll
    for (int i = 0; i < 16; i++) o += hs[r][i] * W2[i * 16 + j];
    tx[row * 16 + j] = o;
}

// ---------------------------------------------------------------------------
// match_k: Sinkhorn (in smem) + either apply-plan (mode 0, writes Sa fp16)
// or score (mode 1, writes out). One block per pair, 256 threads.
// ---------------------------------------------------------------------------
__global__ void match_k(const float* __restrict__ tx, const float* __restrict__ Sb,
                        __half* __restrict__ Sa, float* __restrict__ out, int mode)
{
    __shared__ float mq[20][16], mc[20][16], la[20][20], red[256];
    __shared__ float tile[18][256];
    int b = blockIdx.x, t = threadIdx.x;  // 256 threads
    for (int i = t; i < 320; i += 256) {
        int r = i >> 4, c = i & 15;
        mq[r][c] = (r < 15) ? tx[((size_t)(2 * b) * 18 + r) * 16 + c] : 0.f;
        mc[r][c] = (r < 18) ? tx[((size_t)(2 * b + 1) * 18 + r) * 16 + c] : 0.f;
    }
    __syncthreads();
    for (int i = t; i < 400; i += 256) {
        int q = i / 20, c = i % 20;
        float s = 0.f;
#pragma unroll
        for (int k = 0; k < 16; k++) s += mq[q][k] * mc[c][k];
        la[q][c] = s * 10.f;  // / SINKHORN_TEMP
    }
    __syncthreads();
    for (int it = 0; it < 10; ++it) {
        if (t < 20) {
            float m = -1e30f;
            for (int c = 0; c < 20; c++) m = fmaxf(m, la[t][c]);
            float s = 0.f;
            for (int c = 0; c < 20; c++) s += expf(la[t][c] - m);
            red[t] = logf(s) + m;
        }
        __syncthreads();
        for (int i = t; i < 400; i += 256) la[i / 20][i % 20] -= red[i / 20];
        __syncthreads();
        if (t < 20) {
            float m = -1e30f;
            for (int q = 0; q < 20; q++) m = fmaxf(m, la[q][t]);
            float s = 0.f;
            for (int q = 0; q < 20; q++) s += expf(la[q][t] - m);
            red[t] = logf(s) + m;
        }
        __syncthreads();
        for (int i = t; i < 400; i += 256) la[i / 20][i % 20] -= red[i % 20];
        __syncthreads();
    }
    for (int i = t; i < 400; i += 256) la[i / 20][i % 20] = expf(la[i / 20][i % 20]);
    __syncthreads();

    if (mode == 0) {
        // apply plan to both sides, fp16 output
        for (int side = 0; side < 2; side++) {
            size_t in_base  = ((size_t)(2 * b) + (side == 0 ? 1 : 0)) * 18 * 768;
            size_t out_base = ((size_t)(2 * b) + side) * 18 * 768;
            for (int ch = 0; ch < 3; ch++) {
                __syncthreads();
                int c0 = ch * 256;
                for (int i = t; i < 1152; i += 256) {
                    int r = i / 64, q = i % 64;
                    reinterpret_cast<float4*>(&tile[r][0])[q] =
                        *reinterpret_cast<const float4*>(&Sb[in_base + (size_t)r * 768 + c0 + q * 4]);
                }
                __syncthreads();
                for (int s = 0; s < 18; s++) {
                    float acc = 0.f;
#pragma unroll
                    for (int r = 0; r < 18; r++) {
                        float wv = (side == 0) ? la[s][r] : la[r][s];
                        acc += wv * tile[r][t];
                    }
                    Sa[out_base + (size_t)s * 768 + c0 + t] = __float2half_rn(acc);
                }
            }
        }
    } else {
        // score: -sum_{q<20,k<16} relu(mq - plan @ mc)  (padded q rows DO contribute)
        float local = 0.f;
        for (int i = t; i < 320; i += 256) {
            int q = i >> 4, k = i & 15;
            float pm = 0.f;
#pragma unroll
            for (int c = 0; c < 20; c++) pm += la[q][c] * mc[c][k];
            local += fmaxf(mq[q][k] - pm, 0.f);
        }
        red[t] = local;
        __syncthreads();
        for (int s = 128; s > 0; s >>= 1) {
            if (t < s) red[t] += red[t + s];
            __syncthreads();
        }
        if (t == 0) out[b] = -red[0];
    }
}

// ---------------------------------------------------------------------------
// Launch
// ---------------------------------------------------------------------------
extern "C" void kernel_launch(void* const* d_in, const int* in_sizes, int n_in,
                              void* d_out, int out_size)
{
    const float* node_features = (const float*)d_in[0];
    const float* edge_features = (const float*)d_in[1];
    const float* mult          = (const float*)d_in[2];  (void)mult;
    const float* W_ne = (const float*)d_in[3];  const float* b_ne = (const float*)d_in[4];
    const float* W_ee = (const float*)d_in[5];  const float* b_ee = (const float*)d_in[6];
    const float* W_m1 = (const float*)d_in[7];  const float* b_m1 = (const float*)d_in[8];
    const float* W_m2 = (const float*)d_in[9];  const float* b_m2 = (const float*)d_in[10];
    const float* W_u1 = (const float*)d_in[11]; const float* b_u1 = (const float*)d_in[12];
    const float* W_u2 = (const float*)d_in[13]; const float* b_u2 = (const float*)d_in[14];
    const float* W_c1 = (const float*)d_in[15]; const float* b_c1 = (const float*)d_in[16];
    const float* W_c2 = (const float*)d_in[17]; const float* b_c2 = (const float*)d_in[18];
    const float* W_t1 = (const float*)d_in[19]; const float* b_t1 = (const float*)d_in[20];
    const float* W_t2 = (const float*)d_in[21]; const float* b_t2 = (const float*)d_in[22];
    const int* from_idx = (const int*)d_in[23];
    const int* to_idx   = (const int*)d_in[24];
    float* out = (float*)d_out;

    cudaFuncSetAttribute(hmma_gemm, cudaFuncAttributeMaxDynamicSharedMemorySize, SMEM_DYN);

    float* scratch = nullptr;
    cudaGetSymbolAddress((void**)&scratch, SCRATCH);
    __half* SaH = (__half*)(scratch + OF_SA);
    float* Sb = scratch + OF_SB;
    __half* SbH = (__half*)(scratch + OF_SBH);
    __half* Hb = (__half*)(scratch + OF_H);
    __half* Cb = (__half*)(scratch + OF_COMB);
    float* Ag = scratch + OF_AGG;
    __half* H0 = (__half*)(scratch + OF_H0);
    __half* Gb = (__half*)(scratch + OF_G);
    float* Tx = scratch + OF_TX;
    __half* Uv = (__half*)(scratch + OF_UV);
    __half* WF = (__half*)(scratch + OF_WF);

    // --- init (launch index 3 = first hmma_gemm) ---
    node_enc<<<18432, 256>>>(node_features, W_ne, b_ne, H0);
    prep_uv<<<1, 256>>>(W_ee, b_ee, W_m1, b_m1, Uv);
    prep_wfrag<<<256, 256>>>(W_c1, 256, 256, 256, 0, WF + WF_C1);
    // t=0, p=1: A1 = H0 (fp16), K=128 (inter == 0)
    hmma_gemm<<<dim3(288, 2), 256, SMEM_DYN>>>(
        H0, 128, 1, nullptr, 0, 0, 128,
        WF + WF_C1, 256, b_c1, Hb, 256, 1, nullptr, 128, 1, 0,
        nullptr, nullptr, nullptr, nullptr, nullptr, nullptr, 0);
    prep_wfrag<<<128, 256>>>(W_c2, 256, 128, 128, 0, WF + WF_C2);
    prep_wfrag<<<128, 256>>>(W_m1, 128, 256, 512, 0, WF + WF_M1);
    prep_wfrag<<<128, 256>>>(W_m1 + 128 * 256, 128, 256, 512, 256, WF + WF_M1);
    prep_wfrag<<<128, 256>>>(W_m2, 256, 128, 128, 0, WF + WF_M2);
    prep_wfrag<<<256, 256>>>(W_u1, 256, 256, 256, 0, WF + WF_U1);
    prep_wfrag<<<128, 256>>>(W_u2, 256, 128, 128, 0, WF + WF_U2);
    zero_sb0<<<18432, 256>>>(Sb);

    for (int t = 0; t < 3; t++) {
        for (int p = 1; p <= 5; p++) {
            // C1: Hb = relu([h, inter] @ W_c1 + b_c1) — all-async A
            if (!(t == 0 && p == 1)) {
                const void* hsrc = (p == 1) ? (const void*)H0
                                            : (const void*)(SbH + (size_t)(p - 1) * 128);
                int kC1 = (t == 0) ? 128 : 256;
                hmma_gemm<<<dim3(288, 2), 256, SMEM_DYN>>>(
                    hsrc, (p == 1) ? 128L : 768L, 1, SaH + (size_t)(p - 1) * 128, 768, 1, 128,
                    WF + WF_C1, 256, b_c1, Hb, 256, 1, nullptr, kC1, 1, 0,
                    nullptr, nullptr, nullptr, nullptr, nullptr, nullptr, 0);
            }
            // C2: Cb = Hb @ W_c2 + b_c2 (fp16 in/out)
            hmma_gemm<<<dim3(288, 1), 256, SMEM_DYN>>>(
                Hb, 256, 1, nullptr, 0, 0, 256,
                WF + WF_C2, 128, b_c2, Cb, 128, 1, nullptr, 256, 0, 0,
                nullptr, nullptr, nullptr, nullptr, nullptr, nullptr, 0);
            // M1: Gb = Cb @ [W_m1a | W_m1b] (fp16 in/out, N=512); also zero Ag
            hmma_gemm<<<dim3(288, 4), 256, SMEM_DYN>>>(
                Cb, 128, 1, nullptr, 0, 0, 128,
                WF + WF_M1, 512, nullptr, Gb, 512, 1, nullptr, 128, 0, 0,
                nullptr, nullptr, nullptr, nullptr, nullptr, Ag, 4718592L);
            // edge GEMM -> fp32 atomic agg (fp16 gathers)
            hmma_gemm<<<dim3(720, 1), 256, SMEM_DYN>>>(
                nullptr, 0, 0, nullptr, 0, 0, 256,
                WF + WF_M2, 128, b_m2, Ag, 128, 0, nullptr, 256, 0, 1,
                Gb, from_idx, to_idx, edge_features, Uv, nullptr, 0);
            // U1: Hb = relu([Cb(fp16), Ag(fp32)] @ W_u1 + b_u1)
            hmma_gemm<<<dim3(288, 2), 256, SMEM_DYN>>>(
                Cb, 128, 1, Ag, 128, 0, 128,
                WF + WF_U1, 256, b_u1, Hb, 256, 1, nullptr, 256, 1, 0,
                nullptr, nullptr, nullptr, nullptr, nullptr, nullptr, 0);
            // U2: Sb block p (fp32) + SbH mirror (fp16) = Hb @ W_u2 + b_u2
            hmma_gemm<<<dim3(288, 1), 256, SMEM_DYN>>>(
                Hb, 256, 1, nullptr, 0, 0, 256,
                WF + WF_U2, 128, b_u2, Sb + (size_t)p * 128, 768, 0,
                SbH + (size_t)p * 128, 256, 0, 0,
                nullptr, nullptr, nullptr, nullptr, nullptr, nullptr, 0);
        }
        transform_k<<<4608, 128>>>(Sb, W_t1, b_t1, W_t2, b_t2, Tx);
        // sinkhorn (+apply at t<2, +score at t=2) fused
        match_k<<<1024, 256>>>(Tx, Sb, SaH, out, (t < 2) ? 0 : 1);
    }
}